// round 2
// baseline (speedup 1.0000x reference)
#include <cuda_runtime.h>
#include <cstdint>

// Problem constants (match reference init_kwargs)
static constexpr int H = 1080;
static constexpr int W = 1920;
static constexpr int NPIX = H * W;
static constexpr float ZNEAR = 0.2f;
static constexpr float SH_C0 = 0.28209479177387814f;

// Scratch z-buffer: (depth_bits << 32) | point_index, resolved by atomicMin.
__device__ unsigned long long g_zbuf[NPIX];

// ---------------------------------------------------------------------------
// Pass 1: initialize z-buffer keys to (inf, N)  [miss sentinel]
// ---------------------------------------------------------------------------
__global__ void init_zbuf_kernel(unsigned long long initkey) {
    int p = blockIdx.x * blockDim.x + threadIdx.x;
    if (p < NPIX) g_zbuf[p] = initkey;
}

// ---------------------------------------------------------------------------
// Pass 2: project all points, atomicMin (depth, idx) into pixel buckets.
// All arithmetic uses explicit round-to-nearest intrinsics (no FMA fusion)
// so results are bit-exact with the reference's per-op float32 evaluation.
// (Off-diagonal matrix entries are exactly 0.0f, so summation order is
// irrelevant: adding an exact ±0 product never perturbs the result.)
// ---------------------------------------------------------------------------
__global__ void project_kernel(const float* __restrict__ means3D,
                               const float* __restrict__ viewmatrix,
                               const float* __restrict__ projmatrix,
                               int n) {
    int i = blockIdx.x * blockDim.x + threadIdx.x;
    if (i >= n) return;

    float x = means3D[3 * i + 0];
    float y = means3D[3 * i + 1];
    float z = means3D[3 * i + 2];

    // ph = [x y z 1] @ projmatrix (row-vector convention); cols 0,1,3 needed.
    float phx = __fadd_rn(__fadd_rn(__fmul_rn(x, __ldg(&projmatrix[0])),
                                    __fmul_rn(y, __ldg(&projmatrix[4]))),
                          __fadd_rn(__fmul_rn(z, __ldg(&projmatrix[8])),
                                    __ldg(&projmatrix[12])));
    float phy = __fadd_rn(__fadd_rn(__fmul_rn(x, __ldg(&projmatrix[1])),
                                    __fmul_rn(y, __ldg(&projmatrix[5]))),
                          __fadd_rn(__fmul_rn(z, __ldg(&projmatrix[9])),
                                    __ldg(&projmatrix[13])));
    float phw = __fadd_rn(__fadd_rn(__fmul_rn(x, __ldg(&projmatrix[3])),
                                    __fmul_rn(y, __ldg(&projmatrix[7]))),
                          __fadd_rn(__fmul_rn(z, __ldg(&projmatrix[11])),
                                    __ldg(&projmatrix[15])));

    float inv_w = __fdiv_rn(1.0f, __fadd_rn(phw, 1e-7f));

    // depth = ([x y z 1] @ viewmatrix)[2]
    float depth = __fadd_rn(__fadd_rn(__fmul_rn(x, __ldg(&viewmatrix[2])),
                                      __fmul_rn(y, __ldg(&viewmatrix[6]))),
                            __fadd_rn(__fmul_rn(z, __ldg(&viewmatrix[10])),
                                      __ldg(&viewmatrix[14])));

    // ndc2Pix, per-op float32, round-half-to-even (matches jnp.round)
    float ndcx = __fmul_rn(phx, inv_w);
    float ndcy = __fmul_rn(phy, inv_w);
    float fx = __fsub_rn(__fmul_rn(__fmul_rn(__fadd_rn(ndcx, 1.0f),
                                             (float)W), 0.5f), 0.5f);
    float fy = __fsub_rn(__fmul_rn(__fmul_rn(__fadd_rn(ndcy, 1.0f),
                                             (float)H), 0.5f), 0.5f);

    // Guard the float->int cast against overflow before range checks.
    if (!(depth > ZNEAR)) return;
    if (!(fx > -2.0f && fx < (float)(W + 1) && fy > -2.0f && fy < (float)(H + 1)))
        return;
    int px = (int)rintf(fx);
    int py = (int)rintf(fy);
    if (px < 0 || px >= W || py < 0 || py >= H) return;

    unsigned long long key =
        ((unsigned long long)__float_as_uint(depth) << 32) | (unsigned)i;
    atomicMin(&g_zbuf[py * W + px], key);
}

// ---------------------------------------------------------------------------
// Pass 3: resolve per pixel, write all outputs
// out layout (floats): idx[NPIX] | col[NPIX*3] | depth[NPIX] | feat[NPIX*F]
// ---------------------------------------------------------------------------
__global__ void resolve_kernel(const float* __restrict__ shs, int shs_stride,
                               const float* __restrict__ feat, int F,
                               const float* __restrict__ bg,
                               float* __restrict__ out, int n) {
    int p = blockIdx.x * blockDim.x + threadIdx.x;
    if (p >= NPIX) return;

    unsigned long long key = g_zbuf[p];
    unsigned idx = (unsigned)(key & 0xFFFFFFFFull);

    float* __restrict__ o_idx  = out;
    float* __restrict__ o_col  = out + (size_t)NPIX;
    float* __restrict__ o_dep  = out + (size_t)4 * NPIX;
    float* __restrict__ o_feat = out + (size_t)5 * NPIX;

    if (idx < (unsigned)n) {
        float d = __uint_as_float((unsigned)(key >> 32));
        o_idx[p] = (float)idx;
        o_dep[p] = d;
        const float* sh = shs + (size_t)idx * shs_stride;
        #pragma unroll
        for (int c = 0; c < 3; c++)
            o_col[(size_t)p * 3 + c] =
                fmaxf(__fadd_rn(__fmul_rn(SH_C0, __ldg(&sh[c])), 0.5f), 0.0f);
        const float4* __restrict__ fv =
            (const float4*)(feat + (size_t)idx * F);
        float4* __restrict__ of = (float4*)(o_feat + (size_t)p * F);
        #pragma unroll 8
        for (int i = 0; i < F / 4; i++) of[i] = __ldg(&fv[i]);
    } else {
        o_idx[p] = -1.0f;
        o_dep[p] = 0.0f;
        float b0 = __ldg(&bg[0]), b1 = __ldg(&bg[1]), b2 = __ldg(&bg[2]);
        o_col[(size_t)p * 3 + 0] = b0;
        o_col[(size_t)p * 3 + 1] = b1;
        o_col[(size_t)p * 3 + 2] = b2;
        float4 zv = make_float4(0.f, 0.f, 0.f, 0.f);
        float4* __restrict__ of = (float4*)(o_feat + (size_t)p * F);
        #pragma unroll 8
        for (int i = 0; i < F / 4; i++) of[i] = zv;
    }
}

// ---------------------------------------------------------------------------
// Launch. Input order (metadata): means3D, normal, means2D, feature_vector,
// shs, scales, rotations, viewmatrix, projmatrix, bg, campos
// ---------------------------------------------------------------------------
extern "C" void kernel_launch(void* const* d_in, const int* in_sizes, int n_in,
                              void* d_out, int out_size) {
    const float* means3D    = (const float*)d_in[0];
    const float* feat       = (const float*)d_in[3];
    const float* shs        = (const float*)d_in[4];
    const float* viewmatrix = (const float*)d_in[7];
    const float* projmatrix = (const float*)d_in[8];
    const float* bg         = (const float*)d_in[9];

    int n = in_sizes[0] / 3;
    int F = in_sizes[3] / n;           // 32
    int shs_stride = in_sizes[4] / n;  // K*3 = 48

    unsigned long long initkey =
        ((unsigned long long)0x7F800000u << 32) | (unsigned)n;

    {
        int threads = 256;
        int blocks = (NPIX + threads - 1) / threads;
        init_zbuf_kernel<<<blocks, threads>>>(initkey);
    }
    {
        int threads = 256;
        int blocks = (n + threads - 1) / threads;
        project_kernel<<<blocks, threads>>>(means3D, viewmatrix, projmatrix, n);
    }
    {
        int threads = 256;
        int blocks = (NPIX + threads - 1) / threads;
        resolve_kernel<<<blocks, threads>>>(shs, shs_stride, feat, F, bg,
                                            (float*)d_out, n);
    }
}

// round 3
// speedup vs baseline: 1.4534x; 1.4534x over previous
#include <cuda_runtime.h>
#include <cstdint>

// Problem constants (match reference init_kwargs)
static constexpr int H = 1080;
static constexpr int W = 1920;
static constexpr int NPIX = H * W;           // 2,073,600 = 8100 * 256
static constexpr float ZNEAR = 0.2f;
static constexpr float SH_C0 = 0.28209479177387814f;

// Scratch z-buffer: (depth_bits << 32) | point_index, resolved by atomicMin.
__device__ unsigned long long g_zbuf[NPIX];

// ---------------------------------------------------------------------------
// Pass 1: initialize z-buffer keys to (inf, N). 32B per thread, vectorized.
// NPIX * 8B / 32B = 518400 threads = 2025 blocks of 256.
// ---------------------------------------------------------------------------
__global__ void init_zbuf_kernel(unsigned long long initkey) {
    int t = blockIdx.x * blockDim.x + threadIdx.x;
    ulonglong2 v = make_ulonglong2(initkey, initkey);
    ulonglong2* p = reinterpret_cast<ulonglong2*>(g_zbuf) + 2 * t;
    p[0] = v;
    p[1] = v;
}

// ---------------------------------------------------------------------------
// Pass 2: project all points, atomicMin (depth, idx) into pixel buckets.
// Explicit round-to-nearest intrinsics (no FMA fusion) => bit-exact with the
// reference's per-op float32 evaluation (off-diagonal terms are exactly 0).
// ---------------------------------------------------------------------------
__global__ void project_kernel(const float* __restrict__ means3D,
                               const float* __restrict__ viewmatrix,
                               const float* __restrict__ projmatrix,
                               int n) {
    int i = blockIdx.x * blockDim.x + threadIdx.x;
    if (i >= n) return;

    float x = means3D[3 * i + 0];
    float y = means3D[3 * i + 1];
    float z = means3D[3 * i + 2];

    float phx = __fadd_rn(__fadd_rn(__fmul_rn(x, __ldg(&projmatrix[0])),
                                    __fmul_rn(y, __ldg(&projmatrix[4]))),
                          __fadd_rn(__fmul_rn(z, __ldg(&projmatrix[8])),
                                    __ldg(&projmatrix[12])));
    float phy = __fadd_rn(__fadd_rn(__fmul_rn(x, __ldg(&projmatrix[1])),
                                    __fmul_rn(y, __ldg(&projmatrix[5]))),
                          __fadd_rn(__fmul_rn(z, __ldg(&projmatrix[9])),
                                    __ldg(&projmatrix[13])));
    float phw = __fadd_rn(__fadd_rn(__fmul_rn(x, __ldg(&projmatrix[3])),
                                    __fmul_rn(y, __ldg(&projmatrix[7]))),
                          __fadd_rn(__fmul_rn(z, __ldg(&projmatrix[11])),
                                    __ldg(&projmatrix[15])));

    float inv_w = __fdiv_rn(1.0f, __fadd_rn(phw, 1e-7f));

    float depth = __fadd_rn(__fadd_rn(__fmul_rn(x, __ldg(&viewmatrix[2])),
                                      __fmul_rn(y, __ldg(&viewmatrix[6]))),
                            __fadd_rn(__fmul_rn(z, __ldg(&viewmatrix[10])),
                                      __ldg(&viewmatrix[14])));

    float ndcx = __fmul_rn(phx, inv_w);
    float ndcy = __fmul_rn(phy, inv_w);
    float fx = __fsub_rn(__fmul_rn(__fmul_rn(__fadd_rn(ndcx, 1.0f),
                                             (float)W), 0.5f), 0.5f);
    float fy = __fsub_rn(__fmul_rn(__fmul_rn(__fadd_rn(ndcy, 1.0f),
                                             (float)H), 0.5f), 0.5f);

    if (!(depth > ZNEAR)) return;
    if (!(fx > -2.0f && fx < (float)(W + 1) && fy > -2.0f && fy < (float)(H + 1)))
        return;
    int px = (int)rintf(fx);
    int py = (int)rintf(fy);
    if (px < 0 || px >= W || py < 0 || py >= H) return;

    unsigned long long key =
        ((unsigned long long)__float_as_uint(depth) << 32) | (unsigned)i;
    atomicMin(&g_zbuf[py * W + px], key);
}

// ---------------------------------------------------------------------------
// Pass 3: resolve. One block = 256 consecutive pixels (NPIX = 8100*256).
// All output stores are fully coalesced per instruction.
// out layout (floats): idx[NPIX] | col[NPIX*3] | depth[NPIX] | feat[NPIX*32]
// ---------------------------------------------------------------------------
__global__ __launch_bounds__(256) void resolve_kernel(
        const float* __restrict__ shs,        // stride 48 floats
        const float* __restrict__ feat,       // stride 32 floats
        const float* __restrict__ bg,
        float* __restrict__ out, int n) {
    __shared__ unsigned s_idx[256];

    int t = threadIdx.x;
    int p0 = blockIdx.x * 256;
    int p = p0 + t;

    float* __restrict__ o_idx  = out;
    float* __restrict__ o_col  = out + (size_t)NPIX;
    float* __restrict__ o_dep  = out + (size_t)4 * NPIX;
    float* __restrict__ o_feat = out + (size_t)5 * NPIX;

    unsigned long long key = g_zbuf[p];
    unsigned idx = (unsigned)(key & 0xFFFFFFFFull);
    s_idx[t] = idx;

    bool hit = idx < (unsigned)n;
    o_idx[p] = hit ? (float)idx : -1.0f;
    o_dep[p] = hit ? __uint_as_float((unsigned)(key >> 32)) : 0.0f;

    __syncthreads();

    // Color: 3 rounds of 256 contiguous floats. j = channel-major flat index.
    #pragma unroll
    for (int r = 0; r < 3; r++) {
        int j = r * 256 + t;          // 0..767
        int pix = j / 3;
        int c = j - pix * 3;
        unsigned id2 = s_idx[pix];
        float v;
        if (id2 < (unsigned)n) {
            v = fmaxf(__fadd_rn(__fmul_rn(SH_C0,
                        __ldg(&shs[(size_t)id2 * 48 + c])), 0.5f), 0.0f);
        } else {
            v = __ldg(&bg[c]);
        }
        o_col[(size_t)p0 * 3 + j] = v;
    }

    // Features: 8 rounds; 8 threads per pixel, one float4 chunk each.
    // Loads: 8 threads read one contiguous 128B row. Stores: 4KB contiguous.
    int pix_in_round = t >> 3;        // 0..31
    int chunk = t & 7;                // 0..7
    #pragma unroll
    for (int r = 0; r < 8; r++) {
        int pix = r * 32 + pix_in_round;      // 0..255
        unsigned id2 = s_idx[pix];
        float4 v;
        if (id2 < (unsigned)n) {
            v = __ldg(&reinterpret_cast<const float4*>(
                        feat + (size_t)id2 * 32)[chunk]);
        } else {
            v = make_float4(0.f, 0.f, 0.f, 0.f);
        }
        reinterpret_cast<float4*>(o_feat + ((size_t)p0 + pix) * 32)[chunk] = v;
    }
}

// ---------------------------------------------------------------------------
// Launch. Input order (metadata): means3D, normal, means2D, feature_vector,
// shs, scales, rotations, viewmatrix, projmatrix, bg, campos
// ---------------------------------------------------------------------------
extern "C" void kernel_launch(void* const* d_in, const int* in_sizes, int n_in,
                              void* d_out, int out_size) {
    const float* means3D    = (const float*)d_in[0];
    const float* feat       = (const float*)d_in[3];
    const float* shs        = (const float*)d_in[4];
    const float* viewmatrix = (const float*)d_in[7];
    const float* projmatrix = (const float*)d_in[8];
    const float* bg         = (const float*)d_in[9];

    int n = in_sizes[0] / 3;

    unsigned long long initkey =
        ((unsigned long long)0x7F800000u << 32) | (unsigned)n;

    {
        // 32B per thread: NPIX*8 / 32 = 518400 threads
        int threads = 256;
        int blocks = (NPIX * 8 / 32) / threads;   // 2025
        init_zbuf_kernel<<<blocks, threads>>>(initkey);
    }
    {
        int threads = 256;
        int blocks = (n + threads - 1) / threads;
        project_kernel<<<blocks, threads>>>(means3D, viewmatrix, projmatrix, n);
    }
    {
        int threads = 256;
        int blocks = NPIX / 256;                  // 8100, exact
        resolve_kernel<<<blocks, threads>>>(shs, feat, bg, (float*)d_out, n);
    }
}